// round 13
// baseline (speedup 1.0000x reference)
#include <cuda_runtime.h>
#include <math.h>

#define HDIM 512
#define TILE_R 16
#define SEG_L 128          // output days per scan block
#define WARM 384           // warmup days (contraction burn-in; > 1 year)
#define SK 512             // S-convolution taps
#define SPAN_MAX (WARM + SEG_L)   // 512

// ------------------------- scratch (static device globals; no allocs) ------
__device__ float  g_P[27 * 4096];       // transposed partial sums: [j][block]
__device__ float  g_pm[64];             // 27 physical params + derived constants
__device__ float  g_W12p[HDIM * 32];    // folded parnet W1@W2, padded to 32 cols
__device__ float  g_b12p[32];           // folded parnet bias
__device__ float  g_W12r[HDIM * 2];     // folded resnet rW1@rW2
__device__ float  g_b12r[4];            // folded resnet bias

__constant__ float c_SCALES[27] = {400,1,1,1,1,12,10,10,1,1,1,1,1,10,1,1,1,5,1,1,4,1,1,180,1,1,10};

// ------------------------- parameter constraint ----------------------------
__device__ __forceinline__ float clampf(float v, float lo, float hi) {
    return fminf(fmaxf(v, lo), hi);
}
__device__ __forceinline__ float constrain(float v, int j) {
    switch (j) {
        case 0:  return clampf(v, 0.f, 2.f);
        case 1: case 2: case 20: case 21: case 23: case 24: case 25: case 26:
                 return fmaxf(v, 0.f);
        case 4:  return clampf(v, 0.f, 2.5f);
        case 5:  return clampf(v, 0.01f, 3.f);
        case 6:  return clampf(v, -0.2f, 2.1f);
        case 7:  return clampf(v, 0.23f, 3.0f);
        case 8:  return clampf(v, -1.f, 0.f);
        case 9:  return clampf(v, 0.f, 0.7f);
        case 10: case 16: return 1.f / (1.f + expf(-v));
        case 13: return clampf(v, 0.f, 1.0f);
        case 14: return clampf(v, 0.f, 1.2f);
        case 15: return clampf(v, 0.f, 2.5f);
        case 17: return clampf(v, 0.f, 1.f);
        case 19: return clampf(v, 0.f, 1.f / 0.75f);
        default: return v;   // 3, 11, 12, 18, 22
    }
}

// ------------------------- fold both W1@W2 compositions (one launch) -------
__global__ void k_folds(const float* __restrict__ W1p, const float* __restrict__ b1p,
                        const float* __restrict__ W2p, const float* __restrict__ b2p,
                        const float* __restrict__ W1r, const float* __restrict__ b1r,
                        const float* __restrict__ W2r, const float* __restrict__ b2r) {
    __shared__ float sW1[16 * HDIM];       // 32 KB
    __shared__ float sb[32][8];
    int tid = threadIdx.x;
    bool isr = blockIdx.x >= 32;
    const float* W1 = isr ? W1r : W1p;
    const float* b1 = isr ? b1r : b1p;
    const float* W2 = isr ? W2r : W2p;
    const float* b2 = isr ? b2r : b2p;
    float* out  = isr ? g_W12r : g_W12p;
    float* bout = isr ? g_b12r : g_b12p;
    int NOUT = isr ? 2 : 27;
    int OP   = isr ? 2 : 32;       // output pitch
    int blk  = isr ? blockIdx.x - 32 : blockIdx.x;
    int k0 = blk * 16;

    for (int i = tid; i < 16 * HDIM; i += 256)
        sW1[i] = W1[(k0 + (i >> 9)) * HDIM + (i & 511)];
    if (blk == 0) {
        for (int i = tid; i < NOUT * 8; i += 256) {
            int j = i >> 3, l = i & 7;
            float s = 0.f;
            for (int k = l * 64; k < l * 64 + 64; k++)
                s = fmaf(b1[k], W2[k * NOUT + j], s);
            sb[j][l] = s;
        }
    }
    __syncthreads();
    for (int i = tid; i < 16 * OP; i += 256) {
        int kr = i / OP, j = i - kr * OP;
        float s = 0.f;
        if (j < NOUT) {
            const float* w1r = &sW1[kr * HDIM];
            #pragma unroll 4
            for (int m = 0; m < HDIM; m++)
                s = fmaf(w1r[m], W2[m * NOUT + j], s);
        }
        out[(k0 + kr) * OP + j] = s;
    }
    if (blk == 0 && tid < NOUT) {
        float s = b2[tid];
        #pragma unroll
        for (int l = 0; l < 8; l++) s += sb[tid][l];
        bout[tid] = s;
    }
}

// ------------------------- fused parnet: x -> constrained partial sums -----
__global__ void __launch_bounds__(256)
k_parnet(const float* __restrict__ X, const float* __restrict__ W0,
         const float* __restrict__ b0, int T) {
    __shared__ float sH[TILE_R * HDIM];    // 32 KB; reused as partial scratch
    __shared__ float sX[TILE_R][12];
    __shared__ float sP[TILE_R][28];
    int tid = threadIdx.x;
    int warp = tid >> 5, lane = tid & 31;
    int row0 = blockIdx.x * TILE_R;

    if (tid < TILE_R * 12) {
        int r = tid / 12, q = tid - r * 12;
        int gr = row0 + r;
        sX[r][q] = (gr < T) ? X[gr * 12 + q] : 0.f;
    }
    __syncthreads();

    {
        float w0a[12], w0b[12];
        #pragma unroll
        for (int q = 0; q < 12; q++) {
            w0a[q] = W0[q * HDIM + tid];
            w0b[q] = W0[q * HDIM + tid + 256];
        }
        float b0a = b0[tid], b0b = b0[tid + 256];
        #pragma unroll
        for (int r = 0; r < TILE_R; r++) {
            float sa = b0a, sb2 = b0b;
            #pragma unroll
            for (int q = 0; q < 12; q++) {
                float xv = sX[r][q];
                sa  = fmaf(xv, w0a[q], sa);
                sb2 = fmaf(xv, w0b[q], sb2);
            }
            sH[r * HDIM + tid]       = sa  > 0.f ? sa  : expm1f(sa);
            sH[r * HDIM + tid + 256] = sb2 > 0.f ? sb2 : expm1f(sb2);
        }
    }
    __syncthreads();

    float acc[TILE_R];
    #pragma unroll
    for (int r = 0; r < TILE_R; r++) acc[r] = 0.f;
    int kbase = warp * 64;
    #pragma unroll
    for (int kk = 0; kk < 64; kk += 4) {
        int k = kbase + kk;
        float w0 = g_W12p[(k + 0) * 32 + lane];
        float w1 = g_W12p[(k + 1) * 32 + lane];
        float w2 = g_W12p[(k + 2) * 32 + lane];
        float w3 = g_W12p[(k + 3) * 32 + lane];
        #pragma unroll
        for (int r = 0; r < TILE_R; r++) {
            float4 h = *reinterpret_cast<const float4*>(&sH[r * HDIM + k]);
            acc[r] = fmaf(h.x, w0, acc[r]);
            acc[r] = fmaf(h.y, w1, acc[r]);
            acc[r] = fmaf(h.z, w2, acc[r]);
            acc[r] = fmaf(h.w, w3, acc[r]);
        }
    }
    __syncthreads();   // done reading sH
    #pragma unroll
    for (int r = 0; r < TILE_R; r++)
        sH[(warp * TILE_R + r) * 32 + lane] = acc[r];
    __syncthreads();

    for (int i = tid; i < TILE_R * 27; i += 256) {
        int r = i / 27, j = i - r * 27;
        float s = g_b12p[j];
        #pragma unroll
        for (int w = 0; w < 8; w++) s += sH[(w * TILE_R + r) * 32 + j];
        sP[r][j] = (row0 + r < T) ? constrain(s, j) : 0.f;
    }
    __syncthreads();
    if (tid < 27) {
        float s = 0.f;
        #pragma unroll
        for (int r = 0; r < TILE_R; r++) s += sP[r][tid];
        g_P[tid * 4096 + blockIdx.x] = s;   // transposed: coalesced reduce reads
    }
}

// ------------------------- reduce partials -> pm, derived constants --------
__global__ void k_reduce(int nblk, int T) {
    int j = threadIdx.x >> 5, lane = threadIdx.x & 31;
    if (j < 27) {
        float s0 = 0.f, s1 = 0.f, s2 = 0.f, s3 = 0.f;
        const float* row = &g_P[j * 4096];
        int b = lane;
        for (; b + 96 < nblk; b += 128) {
            s0 += row[b]; s1 += row[b + 32]; s2 += row[b + 64]; s3 += row[b + 96];
        }
        for (; b < nblk; b += 32) s0 += row[b];
        float s = (s0 + s1) + (s2 + s3);
        #pragma unroll
        for (int o = 16; o; o >>= 1) s += __shfl_down_sync(0xffffffffu, s, o);
        if (lane == 0) g_pm[j] = s / (float)T * c_SCALES[j];
    }
    __syncthreads();
    if (threadIdx.x == 0) {
        float sd = g_pm[0], fc = g_pm[1], pwp = g_pm[2], tauD = g_pm[3], tau = g_pm[5];
        g_pm[27] = fc * sd;                              // fcap
        g_pm[28] = 1.f / sd;                             // inv soildepth
        g_pm[29] = 1.f / (fc - pwp);                     // inv (FC - PWP)
        g_pm[30] = 1.f / g_pm[10];                       // inv soilthres
        g_pm[31] = 1.f / g_pm[16];                       // inv ETsoilthres
        g_pm[32] = 1.f - 1.f / tau;                      // a (S recurrence)
        g_pm[33] = 1.f / tau;
        g_pm[34] = 1.f / g_pm[7];                        // inv Smax
        float invTauD = (tauD > 0.f) ? 1.f / tauD : 0.f;
        g_pm[35] = invTauD;
        g_pm[36] = 1.f - invTauD;                        // c1: theta=min(st0, st0*c1+c2)
        g_pm[37] = (g_pm[20] <= 1e-8f) ? 1.f : 0.f;      // small CWmax
        g_pm[38] = g_pm[19] / 0.75f;                     // I0/0.75
        g_pm[39] = g_pm[27] * invTauD;                   // c2
    }
}

// ------------------------- mega: day precompute + scan + resnet ------------
// One block per 128-day output segment. Phase A: S-convolution + day
// quantities for [wstart, end) into SMEM (parallel). Phase B: thread 0 runs
// the serial water recurrence out of SMEM (no STG in loop). Phase C: flush
// pp coalesced + in-block resnet -> yhat.
__global__ void __launch_bounds__(256, 1)
k_mega(const float* __restrict__ cin, const float* __restrict__ sw,
       const float* __restrict__ rW0, const float* __restrict__ rb0,
       float* __restrict__ pp, float* __restrict__ yhat, int T) {
    __shared__ float  sx[SPAN_MAX + SK];      // tair window
    __shared__ float  spw[SK + 8];            // a^j table
    __shared__ float4 sA[SPAN_MAX];           // GM, TRG, fD, EV
    __shared__ float4 sB[SPAN_MAX];           // I, R, cap, meltpot
    __shared__ float  sC[SPAN_MAX];           // cold flag
    __shared__ float  sO[SEG_L * 3];          // gpp, et, swn
    __shared__ float  srW0[3 * HDIM];
    __shared__ float  srb0[HDIM];
    __shared__ float  srW12[2 * HDIM];

    int tid = threadIdx.x;
    int start = blockIdx.x * SEG_L;
    if (start >= T) return;
    int end = min(start + SEG_L, T);
    int wstart = max(start - WARM, 0);
    int span = end - wstart;
    int warmlen = start - wstart;

    // resnet weights (overlaps with phase A staging)
    for (int i = tid; i < 3 * HDIM; i += 256) srW0[i] = rW0[i];
    for (int i = tid; i < HDIM; i += 256) srb0[i] = rb0[i];
    for (int i = tid; i < 2 * HDIM; i += 256) {
        int j = i >> 9, k = i & 511;
        srW12[i] = g_W12r[k * 2 + j];
    }

    float tau = g_pm[5];
    float a = 1.f - 1.f / tau, invtau = 1.f / tau;
    float S0 = g_pm[6], invSmax = g_pm[34], Sinit = g_pm[26];

    int nx = span + SK - 1;
    for (int i = tid; i < nx; i += 256) {
        int g = wstart - (SK - 1) + i;
        sx[i] = (g >= 0 && g < T) ? cin[g * 7 + 1] : 0.f;
    }
    for (int j = tid; j <= SK; j += 256) spw[j] = __powf(a, (float)j);
    __syncthreads();

    // ---- phase A: per-day state-independent quantities ----
    {
        float beta = g_pm[4], kappa = g_pm[8], gamma = g_pm[9];
        float bCO2 = g_pm[11], xCO2 = g_pm[12];
        float ETbeta = g_pm[13], ETkappa = g_pm[14], ETchi = g_pm[15];
        float MeltCoef = g_pm[18], CWmax = g_pm[20], ST = g_pm[21], T0p = g_pm[22];
        float Icoef = g_pm[38];

        for (int d = tid; d < span; d += 256) {
            int t = wstart + d;
            int Kt = min(t + 1, SK);
            int off = d + (SK - 1);
            float s0 = 0.f, s1 = 0.f, s2 = 0.f, s3 = 0.f;
            int j = 0;
            for (; j + 4 <= Kt; j += 4) {
                s0 = fmaf(spw[j + 0], sx[off - j - 0], s0);
                s1 = fmaf(spw[j + 1], sx[off - j - 1], s1);
                s2 = fmaf(spw[j + 2], sx[off - j - 2], s2);
                s3 = fmaf(spw[j + 3], sx[off - j - 3], s3);
            }
            for (; j < Kt; j++) s0 = fmaf(spw[j], sx[off - j], s0);
            float S = ((s0 + s1) + (s2 + s3)) * invtau;
            if (t < SK) S = fmaf(spw[t + 1], Sinit, S);
            float fS = fminf(fmaxf(S - S0, 0.f) * invSmax, 1.f);

            float precip = cin[t * 7 + 0], tair = cin[t * 7 + 1], par = cin[t * 7 + 2];
            float vpd = cin[t * 7 + 3], fapar = cin[t * 7 + 4], co2 = cin[t * 7 + 6];

            float fD = fminf(__expf(kappa * vpd), 1.f);
            float fL = __fdividef(1.f, fmaf(gamma, par, 1.f));
            float G = beta * par * fapar * fS * fL;
            float lc = __logf(co2 * (1.f / 380.f));
            float GM = G * fmaf(bCO2, lc, 1.f);
            float fCO2et = fmaf(xCO2, lc, 1.f);
            float TRG = vpd * ETbeta * G * __powf(vpd, -ETkappa) * fCO2et;
            float EV = ETchi * (1.f - fapar) * par;
            float I = (tair > ST) ? precip * fapar * Icoef : 0.f;
            float R = precip - I;
            float cap = CWmax * fapar;
            float meltpot = (tair >= T0p) ? MeltCoef * (tair - T0p) : 0.f;

            sA[d] = make_float4(GM, TRG, fD, EV);
            sB[d] = make_float4(I, R, cap, meltpot);
            sC[d] = (tair < ST) ? 1.f : 0.f;
        }
    }
    __syncthreads();

    // ---- phase B: serial water recurrence (thread 0, all from SMEM) ----
    if (tid == 0) {
        float PWP = g_pm[2], soilthres = g_pm[10], ETst = g_pm[16], ETnu = g_pm[17];
        float invSD = g_pm[28], invRange = g_pm[29], invST = g_pm[30], invETst = g_pm[31];
        float c1 = g_pm[36], c2 = g_pm[39];
        bool smallcw = g_pm[37] > 0.5f;
        float a1 = invSD * invRange, b1 = -PWP * invRange;   // REW = theta*a1 + b1

        float theta = g_pm[23], canw = g_pm[24], snow = g_pm[25];
        float sw0 = sw[0], invsw1 = 1.f / sw[1];

        auto step = [&](const float4 da, const float4 db, float cold,
                        float& gpp, float& et) {
            float REW = fmaf(theta, a1, b1);
            float fWmid = REW * invST;
            float pw = 1.f;
            if (fWmid < 1.f) pw = __powf(fmaxf(fWmid, 1e-12f), ETnu);
            float fW = (REW < soilthres) ? ((REW > 0.01f) ? fWmid : 0.f) : 1.f;
            float fE = fminf(da.z, fW);
            gpp = da.x * fE;
            float transp = da.y * fE * pw;

            float fwm2 = REW * invETst;
            float fWet = (REW < ETst) ? ((REW > 0.01f) ? fwm2 : 0.f) : 1.f;

            float I = db.x, R = db.y, cap = db.z;
            bool over = (I + canw) > cap;
            float tf = smallcw ? (R + I) : (over ? (R + I + canw - cap) : R);
            float canw1 = smallcw ? canw : (over ? cap : canw + I);
            if (canw1 > 1e-8f) fWet = 1.f;
            float evap = da.w * fWet;

            float newsnow = cold * tf;
            tf = tf - newsnow;
            float snn = snow + newsnow;
            float melt = fminf(db.w, snn);
            float snow1 = snn - melt;

            et = transp + evap;
            float etsoil = fmaxf(et - (canw1 + snow1), 0.f);
            float st0 = fmaxf(theta + tf + melt - etsoil, 1e-4f);
            theta = fminf(st0, fmaf(st0, c1, c2));

            canw = fmaxf(canw1 - et, 0.f);
            float rem = fmaxf(et - canw1, 0.f);
            snow = fmaxf(snow1 - rem, 0.f);
        };

        int d = 0;
        #pragma unroll 4
        for (; d < warmlen; d++) {
            float g, e;
            step(sA[d], sB[d], sC[d], g, e);
        }
        #pragma unroll 2
        for (; d < span; d++) {
            float g, e;
            step(sA[d], sB[d], sC[d], g, e);
            int o = d - warmlen;
            sO[3 * o + 0] = g;
            sO[3 * o + 1] = e;
            sO[3 * o + 2] = (theta - sw0) * invsw1;
        }
    }
    __syncthreads();

    // ---- phase C: flush pp + in-block resnet ----
    int nout = end - start;
    for (int i = tid; i < nout * 3; i += 256)
        pp[start * 3 + i] = sO[i];

    int warp = tid >> 5, lane = tid & 31;
    float bb0 = g_b12r[0], bb1 = g_b12r[1];
    for (int r = warp; r < nout; r += 8) {
        float x0 = sO[3 * r], x1 = sO[3 * r + 1], x2 = sO[3 * r + 2];
        float a0 = 0.f, a1r = 0.f;
        #pragma unroll
        for (int kk = 0; kk < 16; kk++) {
            int k = lane + kk * 32;
            float h = srb0[k];
            h = fmaf(x0, srW0[k], h);
            h = fmaf(x1, srW0[HDIM + k], h);
            h = fmaf(x2, srW0[2 * HDIM + k], h);
            h = h > 0.f ? h : expm1f(h);
            a0  = fmaf(h, srW12[k], a0);
            a1r = fmaf(h, srW12[HDIM + k], a1r);
        }
        #pragma unroll
        for (int o = 16; o; o >>= 1) {
            a0  += __shfl_down_sync(0xffffffffu, a0, o);
            a1r += __shfl_down_sync(0xffffffffu, a1r, o);
        }
        if (lane == 0) {
            yhat[(start + r) * 2 + 0] = a0 + bb0;
            yhat[(start + r) * 2 + 1] = a1r + bb1;
        }
    }
}

// ------------------------- launcher ----------------------------------------
extern "C" void kernel_launch(void* const* d_in, const int* in_sizes, int n_in,
                              void* d_out, int out_size) {
    const float* x   = (const float*)d_in[0];
    const float* cin = (const float*)d_in[1];
    const float* sw  = (const float*)d_in[2];
    // d_in[3] = tp (unused)
    const float* pW0 = (const float*)d_in[4];
    const float* pb0 = (const float*)d_in[5];
    const float* pW1 = (const float*)d_in[6];
    const float* pb1 = (const float*)d_in[7];
    const float* pW2 = (const float*)d_in[8];
    const float* pb2 = (const float*)d_in[9];
    const float* rW0 = (const float*)d_in[10];
    const float* rb0 = (const float*)d_in[11];
    const float* rW1 = (const float*)d_in[12];
    const float* rb1 = (const float*)d_in[13];
    const float* rW2 = (const float*)d_in[14];
    const float* rb2 = (const float*)d_in[15];

    int T = in_sizes[0] / 12;
    float* yhat = (float*)d_out;           // [T, 2]
    float* pp = yhat + 2 * T;              // [T, 3]

    int nblk = (T + TILE_R - 1) / TILE_R;
    int nseg = (T + SEG_L - 1) / SEG_L;

    // fold both linear-linear compositions (one launch, independent halves)
    k_folds<<<64, 256>>>(pW1, pb1, pW2, pb2, rW1, rb1, rW2, rb2);

    // parnet (fused): x -> constrained partial sums -> pm
    k_parnet<<<nblk, 256>>>(x, pW0, pb0, T);
    k_reduce<<<1, 27 * 32>>>(nblk, T);

    // PRELES + resnet, fully fused
    k_mega<<<nseg, 256>>>(cin, sw, rW0, rb0, pp, yhat, T);
}

// round 14
// speedup vs baseline: 1.4987x; 1.4987x over previous
#include <cuda_runtime.h>
#include <math.h>

#define HDIM 512
#define TILE_R 16
#define SEG_L 128          // output days per scan block
#define WARM 384           // warmup days (validated: rel_err identical to 512)
#define SK 512             // S-convolution taps

// ------------------------- scratch (static device globals; no allocs) ------
__device__ float  g_P[27 * 4096];       // transposed partial sums: [j][block]
__device__ float  g_pm[64];             // 27 physical params + derived constants
__device__ float  g_W12p[HDIM * 32];    // folded parnet W1@W2, padded to 32 cols
__device__ float  g_b12p[32];           // folded parnet bias
__device__ float  g_W12r[HDIM * 2];     // folded resnet rW1@rW2
__device__ float  g_b12r[4];            // folded resnet bias
__device__ float4 g_dayA[50176];        // {GM, TRG, fD, EV}
__device__ float4 g_dayB[50176];        // {I, R, cap, meltpot}
__device__ __align__(16) float g_dayC[50176];  // cold flag

__constant__ float c_SCALES[27] = {400,1,1,1,1,12,10,10,1,1,1,1,1,10,1,1,1,5,1,1,4,1,1,180,1,1,10};

// ------------------------- parameter constraint ----------------------------
__device__ __forceinline__ float clampf(float v, float lo, float hi) {
    return fminf(fmaxf(v, lo), hi);
}
__device__ __forceinline__ float constrain(float v, int j) {
    switch (j) {
        case 0:  return clampf(v, 0.f, 2.f);
        case 1: case 2: case 20: case 21: case 23: case 24: case 25: case 26:
                 return fmaxf(v, 0.f);
        case 4:  return clampf(v, 0.f, 2.5f);
        case 5:  return clampf(v, 0.01f, 3.f);
        case 6:  return clampf(v, -0.2f, 2.1f);
        case 7:  return clampf(v, 0.23f, 3.0f);
        case 8:  return clampf(v, -1.f, 0.f);
        case 9:  return clampf(v, 0.f, 0.7f);
        case 10: case 16: return 1.f / (1.f + expf(-v));
        case 13: return clampf(v, 0.f, 1.0f);
        case 14: return clampf(v, 0.f, 1.2f);
        case 15: return clampf(v, 0.f, 2.5f);
        case 17: return clampf(v, 0.f, 1.f);
        case 19: return clampf(v, 0.f, 1.f / 0.75f);
        default: return v;   // 3, 11, 12, 18, 22
    }
}

// ------------------------- fold both W1@W2 compositions (one launch) -------
__global__ void k_folds(const float* __restrict__ W1p, const float* __restrict__ b1p,
                        const float* __restrict__ W2p, const float* __restrict__ b2p,
                        const float* __restrict__ W1r, const float* __restrict__ b1r,
                        const float* __restrict__ W2r, const float* __restrict__ b2r) {
    __shared__ float sW1[16 * HDIM];       // 32 KB
    __shared__ float sb[32][8];
    int tid = threadIdx.x;
    bool isr = blockIdx.x >= 32;
    const float* W1 = isr ? W1r : W1p;
    const float* b1 = isr ? b1r : b1p;
    const float* W2 = isr ? W2r : W2p;
    const float* b2 = isr ? b2r : b2p;
    float* out  = isr ? g_W12r : g_W12p;
    float* bout = isr ? g_b12r : g_b12p;
    int NOUT = isr ? 2 : 27;
    int OP   = isr ? 2 : 32;       // output pitch
    int blk  = isr ? blockIdx.x - 32 : blockIdx.x;
    int k0 = blk * 16;

    for (int i = tid; i < 16 * HDIM; i += 256)
        sW1[i] = W1[(k0 + (i >> 9)) * HDIM + (i & 511)];
    if (blk == 0) {
        for (int i = tid; i < NOUT * 8; i += 256) {
            int j = i >> 3, l = i & 7;
            float s = 0.f;
            for (int k = l * 64; k < l * 64 + 64; k++)
                s = fmaf(b1[k], W2[k * NOUT + j], s);
            sb[j][l] = s;
        }
    }
    __syncthreads();
    for (int i = tid; i < 16 * OP; i += 256) {
        int kr = i / OP, j = i - kr * OP;
        float s = 0.f;
        if (j < NOUT) {
            const float* w1r = &sW1[kr * HDIM];
            #pragma unroll 4
            for (int m = 0; m < HDIM; m++)
                s = fmaf(w1r[m], W2[m * NOUT + j], s);
        }
        out[(k0 + kr) * OP + j] = s;
    }
    if (blk == 0 && tid < NOUT) {
        float s = b2[tid];
        #pragma unroll
        for (int l = 0; l < 8; l++) s += sb[tid][l];
        bout[tid] = s;
    }
}

// ------------------------- fused parnet: x -> constrained partial sums -----
__global__ void __launch_bounds__(256)
k_parnet(const float* __restrict__ X, const float* __restrict__ W0,
         const float* __restrict__ b0, int T) {
    __shared__ float sH[TILE_R * HDIM];    // 32 KB; reused as partial scratch
    __shared__ float sX[TILE_R][12];
    __shared__ float sP[TILE_R][28];
    int tid = threadIdx.x;
    int warp = tid >> 5, lane = tid & 31;
    int row0 = blockIdx.x * TILE_R;

    if (tid < TILE_R * 12) {
        int r = tid / 12, q = tid - r * 12;
        int gr = row0 + r;
        sX[r][q] = (gr < T) ? X[gr * 12 + q] : 0.f;
    }
    __syncthreads();

    {
        float w0a[12], w0b[12];
        #pragma unroll
        for (int q = 0; q < 12; q++) {
            w0a[q] = W0[q * HDIM + tid];
            w0b[q] = W0[q * HDIM + tid + 256];
        }
        float b0a = b0[tid], b0b = b0[tid + 256];
        #pragma unroll
        for (int r = 0; r < TILE_R; r++) {
            float sa = b0a, sb2 = b0b;
            #pragma unroll
            for (int q = 0; q < 12; q++) {
                float xv = sX[r][q];
                sa  = fmaf(xv, w0a[q], sa);
                sb2 = fmaf(xv, w0b[q], sb2);
            }
            sH[r * HDIM + tid]       = sa  > 0.f ? sa  : expm1f(sa);
            sH[r * HDIM + tid + 256] = sb2 > 0.f ? sb2 : expm1f(sb2);
        }
    }
    __syncthreads();

    float acc[TILE_R];
    #pragma unroll
    for (int r = 0; r < TILE_R; r++) acc[r] = 0.f;
    int kbase = warp * 64;
    #pragma unroll
    for (int kk = 0; kk < 64; kk += 4) {
        int k = kbase + kk;
        float w0 = g_W12p[(k + 0) * 32 + lane];
        float w1 = g_W12p[(k + 1) * 32 + lane];
        float w2 = g_W12p[(k + 2) * 32 + lane];
        float w3 = g_W12p[(k + 3) * 32 + lane];
        #pragma unroll
        for (int r = 0; r < TILE_R; r++) {
            float4 h = *reinterpret_cast<const float4*>(&sH[r * HDIM + k]);
            acc[r] = fmaf(h.x, w0, acc[r]);
            acc[r] = fmaf(h.y, w1, acc[r]);
            acc[r] = fmaf(h.z, w2, acc[r]);
            acc[r] = fmaf(h.w, w3, acc[r]);
        }
    }
    __syncthreads();   // done reading sH
    #pragma unroll
    for (int r = 0; r < TILE_R; r++)
        sH[(warp * TILE_R + r) * 32 + lane] = acc[r];
    __syncthreads();

    for (int i = tid; i < TILE_R * 27; i += 256) {
        int r = i / 27, j = i - r * 27;
        float s = g_b12p[j];
        #pragma unroll
        for (int w = 0; w < 8; w++) s += sH[(w * TILE_R + r) * 32 + j];
        sP[r][j] = (row0 + r < T) ? constrain(s, j) : 0.f;
    }
    __syncthreads();
    if (tid < 27) {
        float s = 0.f;
        #pragma unroll
        for (int r = 0; r < TILE_R; r++) s += sP[r][tid];
        g_P[tid * 4096 + blockIdx.x] = s;   // transposed: coalesced reduce reads
    }
}

// ------------------------- reduce partials -> pm, derived constants --------
__global__ void k_reduce(int nblk, int T) {
    int j = threadIdx.x >> 5, lane = threadIdx.x & 31;
    if (j < 27) {
        float s0 = 0.f, s1 = 0.f, s2 = 0.f, s3 = 0.f;
        const float* row = &g_P[j * 4096];
        int b = lane;
        for (; b + 96 < nblk; b += 128) {
            s0 += row[b]; s1 += row[b + 32]; s2 += row[b + 64]; s3 += row[b + 96];
        }
        for (; b < nblk; b += 32) s0 += row[b];
        float s = (s0 + s1) + (s2 + s3);
        #pragma unroll
        for (int o = 16; o; o >>= 1) s += __shfl_down_sync(0xffffffffu, s, o);
        if (lane == 0) g_pm[j] = s / (float)T * c_SCALES[j];
    }
    __syncthreads();
    if (threadIdx.x == 0) {
        float sd = g_pm[0], fc = g_pm[1], pwp = g_pm[2], tauD = g_pm[3], tau = g_pm[5];
        g_pm[27] = fc * sd;                              // fcap
        g_pm[28] = 1.f / sd;                             // inv soildepth
        g_pm[29] = 1.f / (fc - pwp);                     // inv (FC - PWP)
        g_pm[30] = 1.f / g_pm[10];                       // inv soilthres
        g_pm[31] = 1.f / g_pm[16];                       // inv ETsoilthres
        g_pm[32] = 1.f - 1.f / tau;                      // a (S recurrence)
        g_pm[33] = 1.f / tau;
        g_pm[34] = 1.f / g_pm[7];                        // inv Smax
        float invTauD = (tauD > 0.f) ? 1.f / tauD : 0.f;
        g_pm[35] = invTauD;
        g_pm[36] = 1.f - invTauD;                        // c1: theta=min(st0, st0*c1+c2)
        g_pm[37] = (g_pm[20] <= 1e-8f) ? 1.f : 0.f;      // small CWmax
        g_pm[38] = g_pm[19] / 0.75f;                     // I0/0.75
        g_pm[39] = g_pm[27] * invTauD;                   // c2
    }
}

// ------------------------- day precompute + S via truncated convolution ----
__global__ void k_day(const float* __restrict__ cin, int T) {
    __shared__ float sx[SK + 256 - 1 + 1];   // tair[base-(SK-1) .. base+255]
    __shared__ float pw[SK + 1];
    int base = blockIdx.x * 256;
    int tid = threadIdx.x;

    float tau = g_pm[5];
    float a = 1.f - 1.f / tau, invtau = 1.f / tau;
    float S0 = g_pm[6], invSmax = g_pm[34], Sinit = g_pm[26];

    for (int i = tid; i < SK + 255; i += 256) {
        int g = base - (SK - 1) + i;
        sx[i] = (g >= 0 && g < T) ? cin[g * 7 + 1] : 0.f;
    }
    for (int j = tid; j <= SK; j += 256) pw[j] = __powf(a, (float)j);
    __syncthreads();

    int t = base + tid;
    if (t >= T) return;

    int Kt = min(t + 1, SK);
    int off = tid + (SK - 1);    // sx index of x_t
    float s0 = 0.f, s1 = 0.f, s2 = 0.f, s3 = 0.f;
    int j = 0;
    for (; j + 4 <= Kt; j += 4) {
        s0 = fmaf(pw[j + 0], sx[off - j - 0], s0);
        s1 = fmaf(pw[j + 1], sx[off - j - 1], s1);
        s2 = fmaf(pw[j + 2], sx[off - j - 2], s2);
        s3 = fmaf(pw[j + 3], sx[off - j - 3], s3);
    }
    for (; j < Kt; j++) s0 = fmaf(pw[j], sx[off - j], s0);
    float S = ((s0 + s1) + (s2 + s3)) * invtau;
    if (t < SK) S = fmaf(pw[t + 1], Sinit, S);
    float fS = fminf(fmaxf(S - S0, 0.f) * invSmax, 1.f);

    float beta = g_pm[4], kappa = g_pm[8], gamma = g_pm[9];
    float bCO2 = g_pm[11], xCO2 = g_pm[12];
    float ETbeta = g_pm[13], ETkappa = g_pm[14], ETchi = g_pm[15];
    float MeltCoef = g_pm[18], CWmax = g_pm[20], ST = g_pm[21], T0p = g_pm[22];
    float Icoef = g_pm[38];

    float precip = cin[t * 7 + 0], tair = cin[t * 7 + 1], par = cin[t * 7 + 2];
    float vpd = cin[t * 7 + 3], fapar = cin[t * 7 + 4], co2 = cin[t * 7 + 6];

    float fD = fminf(__expf(kappa * vpd), 1.f);
    float fL = __fdividef(1.f, fmaf(gamma, par, 1.f));
    float G = beta * par * fapar * fS * fL;
    float lc = __logf(co2 * (1.f / 380.f));
    float GM = G * fmaf(bCO2, lc, 1.f);
    float fCO2et = fmaf(xCO2, lc, 1.f);
    float TRG = vpd * ETbeta * G * __powf(vpd, -ETkappa) * fCO2et;
    float EV = ETchi * (1.f - fapar) * par;
    float I = (tair > ST) ? precip * fapar * Icoef : 0.f;
    float R = precip - I;
    float cap = CWmax * fapar;
    float meltpot = (tair >= T0p) ? MeltCoef * (tair - T0p) : 0.f;

    g_dayA[t] = make_float4(GM, TRG, fD, EV);
    g_dayB[t] = make_float4(I, R, cap, meltpot);
    g_dayC[t] = (tair < ST) ? 1.f : 0.f;
}

// ------------------------- scan + resnet fused -----------------------------
// 256 threads. Thread 0 runs the R11 register-pipelined serial recurrence
// (global day arrays, outputs to SMEM); warps 1-7 stage resnet weights
// concurrently; after one barrier the block flushes pp and computes yhat.
__global__ void __launch_bounds__(256, 1)
k_scanR(const float* __restrict__ sw, const float* __restrict__ rW0,
        const float* __restrict__ rb0, float* __restrict__ pp,
        float* __restrict__ yhat, int T) {
    __shared__ float sO[SEG_L * 3];
    __shared__ float srW0[3 * HDIM];
    __shared__ float srb0[HDIM];
    __shared__ float srW12[2 * HDIM];

    int tid = threadIdx.x;
    int start = blockIdx.x * SEG_L;
    if (start >= T) return;
    int end = min(start + SEG_L, T);
    int wstart = max(start - WARM, 0);

    if (tid >= 32) {
        // stage resnet weights while thread 0 scans
        for (int i = tid - 32; i < 3 * HDIM; i += 224) srW0[i] = rW0[i];
        for (int i = tid - 32; i < HDIM; i += 224) srb0[i] = rb0[i];
        for (int i = tid - 32; i < 2 * HDIM; i += 224) {
            int j = i >> 9, k = i & 511;
            srW12[i] = g_W12r[k * 2 + j];
        }
    } else if (tid == 0) {
        float PWP = g_pm[2], soilthres = g_pm[10], ETst = g_pm[16], ETnu = g_pm[17];
        float invSD = g_pm[28], invRange = g_pm[29], invST = g_pm[30], invETst = g_pm[31];
        float c1 = g_pm[36], c2 = g_pm[39];
        bool smallcw = g_pm[37] > 0.5f;
        float a1 = invSD * invRange, b1 = -PWP * invRange;   // REW = theta*a1 + b1

        float theta = g_pm[23], canw = g_pm[24], snow = g_pm[25];
        float sw0 = sw[0], invsw1 = 1.f / sw[1];

        auto step = [&](const float4 da, const float4 db, float cold,
                        float& gpp, float& et) {
            float REW = fmaf(theta, a1, b1);
            float fWmid = REW * invST;
            float pwin = fmaxf(fminf(fWmid, 1.f), 1e-12f);
            float pw = __powf(pwin, ETnu);
            float fW = (REW < soilthres) ? ((REW > 0.01f) ? fWmid : 0.f) : 1.f;
            float fE = fminf(da.z, fW);
            gpp = da.x * fE;
            float transp = da.y * fE * pw;

            float fwm2 = REW * invETst;
            float fWet = (REW < ETst) ? ((REW > 0.01f) ? fwm2 : 0.f) : 1.f;

            float I = db.x, R = db.y, cap = db.z;
            bool over = (I + canw) > cap;
            float tf = smallcw ? (R + I) : (over ? (R + I + canw - cap) : R);
            float canw1 = smallcw ? canw : (over ? cap : canw + I);
            if (canw1 > 1e-8f) fWet = 1.f;
            float evap = da.w * fWet;

            float newsnow = cold * tf;
            tf = tf - newsnow;
            float snn = snow + newsnow;
            float melt = fminf(db.w, snn);
            float snow1 = snn - melt;

            et = transp + evap;
            float etsoil = fmaxf(et - (canw1 + snow1), 0.f);
            float st0 = fmaxf(theta + tf + melt - etsoil, 1e-4f);
            theta = fminf(st0, fmaf(st0, c1, c2));

            canw = fmaxf(canw1 - et, 0.f);
            float rem = fmaxf(et - canw1, 0.f);
            snow = fmaxf(snow1 - rem, 0.f);
        };

        float4 A0, A1, A2, A3, B0, B1, B2, B3, C;
        int t = wstart;
        if (t + 4 <= end) {
            A0 = g_dayA[t]; A1 = g_dayA[t + 1]; A2 = g_dayA[t + 2]; A3 = g_dayA[t + 3];
            B0 = g_dayB[t]; B1 = g_dayB[t + 1]; B2 = g_dayB[t + 2]; B3 = g_dayB[t + 3];
            C = *reinterpret_cast<const float4*>(&g_dayC[t]);
        }
        // warmup: [wstart, start)
        for (; t + 4 <= start; t += 4) {
            float4 nA0, nA1, nA2, nA3, nB0, nB1, nB2, nB3, nC;
            int tn = t + 4;
            if (tn + 4 <= end) {
                nA0 = g_dayA[tn]; nA1 = g_dayA[tn + 1]; nA2 = g_dayA[tn + 2]; nA3 = g_dayA[tn + 3];
                nB0 = g_dayB[tn]; nB1 = g_dayB[tn + 1]; nB2 = g_dayB[tn + 2]; nB3 = g_dayB[tn + 3];
                nC = *reinterpret_cast<const float4*>(&g_dayC[tn]);
            }
            float g, e;
            step(A0, B0, C.x, g, e);
            step(A1, B1, C.y, g, e);
            step(A2, B2, C.z, g, e);
            step(A3, B3, C.w, g, e);
            A0 = nA0; A1 = nA1; A2 = nA2; A3 = nA3;
            B0 = nB0; B1 = nB1; B2 = nB2; B3 = nB3; C = nC;
        }
        for (; t < start; t++) { float g, e; step(g_dayA[t], g_dayB[t], g_dayC[t], g, e); }
        // output: [start, end) -> SMEM
        for (; t + 4 <= end; t += 4) {
            float4 nA0, nA1, nA2, nA3, nB0, nB1, nB2, nB3, nC;
            int tn = t + 4;
            if (tn + 4 <= end) {
                nA0 = g_dayA[tn]; nA1 = g_dayA[tn + 1]; nA2 = g_dayA[tn + 2]; nA3 = g_dayA[tn + 3];
                nB0 = g_dayB[tn]; nB1 = g_dayB[tn + 1]; nB2 = g_dayB[tn + 2]; nB3 = g_dayB[tn + 3];
                nC = *reinterpret_cast<const float4*>(&g_dayC[tn]);
            }
            int o = t - start;
            float g, e;
            step(A0, B0, C.x, g, e);
            sO[3 * o + 0] = g; sO[3 * o + 1] = e; sO[3 * o + 2] = (theta - sw0) * invsw1;
            step(A1, B1, C.y, g, e);
            sO[3 * o + 3] = g; sO[3 * o + 4] = e; sO[3 * o + 5] = (theta - sw0) * invsw1;
            step(A2, B2, C.z, g, e);
            sO[3 * o + 6] = g; sO[3 * o + 7] = e; sO[3 * o + 8] = (theta - sw0) * invsw1;
            step(A3, B3, C.w, g, e);
            sO[3 * o + 9] = g; sO[3 * o + 10] = e; sO[3 * o + 11] = (theta - sw0) * invsw1;
            A0 = nA0; A1 = nA1; A2 = nA2; A3 = nA3;
            B0 = nB0; B1 = nB1; B2 = nB2; B3 = nB3; C = nC;
        }
        for (; t < end; t++) {   // tail
            float g, e;
            step(g_dayA[t], g_dayB[t], g_dayC[t], g, e);
            int o = t - start;
            sO[3 * o + 0] = g; sO[3 * o + 1] = e; sO[3 * o + 2] = (theta - sw0) * invsw1;
        }
    }
    __syncthreads();

    // flush pp + in-block resnet
    int nout = end - start;
    for (int i = tid; i < nout * 3; i += 256)
        pp[start * 3 + i] = sO[i];

    int warp = tid >> 5, lane = tid & 31;
    float bb0 = g_b12r[0], bb1 = g_b12r[1];
    for (int r = warp; r < nout; r += 8) {
        float x0 = sO[3 * r], x1 = sO[3 * r + 1], x2 = sO[3 * r + 2];
        float a0 = 0.f, a1r = 0.f;
        #pragma unroll
        for (int kk = 0; kk < 16; kk++) {
            int k = lane + kk * 32;
            float h = srb0[k];
            h = fmaf(x0, srW0[k], h);
            h = fmaf(x1, srW0[HDIM + k], h);
            h = fmaf(x2, srW0[2 * HDIM + k], h);
            h = h > 0.f ? h : expm1f(h);
            a0  = fmaf(h, srW12[k], a0);
            a1r = fmaf(h, srW12[HDIM + k], a1r);
        }
        #pragma unroll
        for (int o = 16; o; o >>= 1) {
            a0  += __shfl_down_sync(0xffffffffu, a0, o);
            a1r += __shfl_down_sync(0xffffffffu, a1r, o);
        }
        if (lane == 0) {
            yhat[(start + r) * 2 + 0] = a0 + bb0;
            yhat[(start + r) * 2 + 1] = a1r + bb1;
        }
    }
}

// ------------------------- launcher ----------------------------------------
extern "C" void kernel_launch(void* const* d_in, const int* in_sizes, int n_in,
                              void* d_out, int out_size) {
    const float* x   = (const float*)d_in[0];
    const float* cin = (const float*)d_in[1];
    const float* sw  = (const float*)d_in[2];
    // d_in[3] = tp (unused)
    const float* pW0 = (const float*)d_in[4];
    const float* pb0 = (const float*)d_in[5];
    const float* pW1 = (const float*)d_in[6];
    const float* pb1 = (const float*)d_in[7];
    const float* pW2 = (const float*)d_in[8];
    const float* pb2 = (const float*)d_in[9];
    const float* rW0 = (const float*)d_in[10];
    const float* rb0 = (const float*)d_in[11];
    const float* rW1 = (const float*)d_in[12];
    const float* rb1 = (const float*)d_in[13];
    const float* rW2 = (const float*)d_in[14];
    const float* rb2 = (const float*)d_in[15];

    int T = in_sizes[0] / 12;
    float* yhat = (float*)d_out;           // [T, 2]
    float* pp = yhat + 2 * T;              // [T, 3]

    int nblk = (T + TILE_R - 1) / TILE_R;
    int nseg = (T + SEG_L - 1) / SEG_L;

    // fold both linear-linear compositions (one launch, independent halves)
    k_folds<<<64, 256>>>(pW1, pb1, pW2, pb2, rW1, rb1, rW2, rb2);

    // parnet (fused): x -> constrained partial sums -> pm
    k_parnet<<<nblk, 256>>>(x, pW0, pb0, T);
    k_reduce<<<1, 27 * 32>>>(nblk, T);

    // PRELES day precompute, then scan + resnet fused
    k_day<<<(T + 255) / 256, 256>>>(cin, T);
    k_scanR<<<nseg, 256>>>(sw, rW0, rb0, pp, yhat, T);
}

// round 15
// speedup vs baseline: 1.6641x; 1.1104x over previous
#include <cuda_runtime.h>
#include <math.h>

#define HDIM 512
#define TILE_R 16
#define SEG_L 128          // output days per scan block
#define WARM 384           // warmup days (validated: rel_err identical to 512)
#define SK 512             // S-convolution taps
#define DAYB 128           // days per k_day block

// ------------------------- scratch (static device globals; no allocs) ------
__device__ float  g_P[27 * 4096];       // transposed partial sums: [j][block]
__device__ float  g_pm[32];             // 27 physical params (scaled means)
__device__ float  g_W12p[HDIM * 32];    // folded parnet W1@W2, padded to 32 cols
__device__ float  g_b12p[32];           // folded parnet bias
__device__ float  g_W12r[HDIM * 2];     // folded resnet rW1@rW2
__device__ float  g_b12r[4];            // folded resnet bias
__device__ float4 g_dayA[50176];        // {GM, TRG, fD, EV}
__device__ float4 g_dayB[50176];        // {I, R, cap, meltpot}
__device__ __align__(16) float g_dayC[50176];  // cold flag

__constant__ float c_SCALES[27] = {400,1,1,1,1,12,10,10,1,1,1,1,1,10,1,1,1,5,1,1,4,1,1,180,1,1,10};

// ------------------------- parameter constraint ----------------------------
__device__ __forceinline__ float clampf(float v, float lo, float hi) {
    return fminf(fmaxf(v, lo), hi);
}
__device__ __forceinline__ float constrain(float v, int j) {
    switch (j) {
        case 0:  return clampf(v, 0.f, 2.f);
        case 1: case 2: case 20: case 21: case 23: case 24: case 25: case 26:
                 return fmaxf(v, 0.f);
        case 4:  return clampf(v, 0.f, 2.5f);
        case 5:  return clampf(v, 0.01f, 3.f);
        case 6:  return clampf(v, -0.2f, 2.1f);
        case 7:  return clampf(v, 0.23f, 3.0f);
        case 8:  return clampf(v, -1.f, 0.f);
        case 9:  return clampf(v, 0.f, 0.7f);
        case 10: case 16: return 1.f / (1.f + expf(-v));
        case 13: return clampf(v, 0.f, 1.0f);
        case 14: return clampf(v, 0.f, 1.2f);
        case 15: return clampf(v, 0.f, 2.5f);
        case 17: return clampf(v, 0.f, 1.f);
        case 19: return clampf(v, 0.f, 1.f / 0.75f);
        default: return v;   // 3, 11, 12, 18, 22
    }
}

// ------------------------- fold both W1@W2 compositions (one launch) -------
__global__ void k_folds(const float* __restrict__ W1p, const float* __restrict__ b1p,
                        const float* __restrict__ W2p, const float* __restrict__ b2p,
                        const float* __restrict__ W1r, const float* __restrict__ b1r,
                        const float* __restrict__ W2r, const float* __restrict__ b2r) {
    __shared__ float sW1[16 * HDIM];       // 32 KB
    __shared__ float sb[32][8];
    int tid = threadIdx.x;
    bool isr = blockIdx.x >= 32;
    const float* W1 = isr ? W1r : W1p;
    const float* b1 = isr ? b1r : b1p;
    const float* W2 = isr ? W2r : W2p;
    const float* b2 = isr ? b2r : b2p;
    float* out  = isr ? g_W12r : g_W12p;
    float* bout = isr ? g_b12r : g_b12p;
    int NOUT = isr ? 2 : 27;
    int OP   = isr ? 2 : 32;       // output pitch
    int blk  = isr ? blockIdx.x - 32 : blockIdx.x;
    int k0 = blk * 16;

    for (int i = tid; i < 16 * HDIM; i += 256)
        sW1[i] = W1[(k0 + (i >> 9)) * HDIM + (i & 511)];
    if (blk == 0) {
        for (int i = tid; i < NOUT * 8; i += 256) {
            int j = i >> 3, l = i & 7;
            float s = 0.f;
            for (int k = l * 64; k < l * 64 + 64; k++)
                s = fmaf(b1[k], W2[k * NOUT + j], s);
            sb[j][l] = s;
        }
    }
    __syncthreads();
    for (int i = tid; i < 16 * OP; i += 256) {
        int kr = i / OP, j = i - kr * OP;
        float s = 0.f;
        if (j < NOUT) {
            const float* w1r = &sW1[kr * HDIM];
            #pragma unroll 4
            for (int m = 0; m < HDIM; m++)
                s = fmaf(w1r[m], W2[m * NOUT + j], s);
        }
        out[(k0 + kr) * OP + j] = s;
    }
    if (blk == 0 && tid < NOUT) {
        float s = b2[tid];
        #pragma unroll
        for (int l = 0; l < 8; l++) s += sb[tid][l];
        bout[tid] = s;
    }
}

// ------------------------- fused parnet: x -> constrained partial sums -----
__global__ void __launch_bounds__(256)
k_parnet(const float* __restrict__ X, const float* __restrict__ W0,
         const float* __restrict__ b0, int T) {
    __shared__ float sH[TILE_R * HDIM];    // 32 KB; reused as partial scratch
    __shared__ float sX[TILE_R][12];
    __shared__ float sP[TILE_R][28];
    int tid = threadIdx.x;
    int warp = tid >> 5, lane = tid & 31;
    int row0 = blockIdx.x * TILE_R;

    if (tid < TILE_R * 12) {
        int r = tid / 12, q = tid - r * 12;
        int gr = row0 + r;
        sX[r][q] = (gr < T) ? X[gr * 12 + q] : 0.f;
    }
    __syncthreads();

    {
        float w0a[12], w0b[12];
        #pragma unroll
        for (int q = 0; q < 12; q++) {
            w0a[q] = W0[q * HDIM + tid];
            w0b[q] = W0[q * HDIM + tid + 256];
        }
        float b0a = b0[tid], b0b = b0[tid + 256];
        #pragma unroll
        for (int r = 0; r < TILE_R; r++) {
            float sa = b0a, sb2 = b0b;
            #pragma unroll
            for (int q = 0; q < 12; q++) {
                float xv = sX[r][q];
                sa  = fmaf(xv, w0a[q], sa);
                sb2 = fmaf(xv, w0b[q], sb2);
            }
            sH[r * HDIM + tid]       = sa  > 0.f ? sa  : expm1f(sa);
            sH[r * HDIM + tid + 256] = sb2 > 0.f ? sb2 : expm1f(sb2);
        }
    }
    __syncthreads();

    float acc[TILE_R];
    #pragma unroll
    for (int r = 0; r < TILE_R; r++) acc[r] = 0.f;
    int kbase = warp * 64;
    #pragma unroll
    for (int kk = 0; kk < 64; kk += 4) {
        int k = kbase + kk;
        float w0 = g_W12p[(k + 0) * 32 + lane];
        float w1 = g_W12p[(k + 1) * 32 + lane];
        float w2 = g_W12p[(k + 2) * 32 + lane];
        float w3 = g_W12p[(k + 3) * 32 + lane];
        #pragma unroll
        for (int r = 0; r < TILE_R; r++) {
            float4 h = *reinterpret_cast<const float4*>(&sH[r * HDIM + k]);
            acc[r] = fmaf(h.x, w0, acc[r]);
            acc[r] = fmaf(h.y, w1, acc[r]);
            acc[r] = fmaf(h.z, w2, acc[r]);
            acc[r] = fmaf(h.w, w3, acc[r]);
        }
    }
    __syncthreads();   // done reading sH
    #pragma unroll
    for (int r = 0; r < TILE_R; r++)
        sH[(warp * TILE_R + r) * 32 + lane] = acc[r];
    __syncthreads();

    for (int i = tid; i < TILE_R * 27; i += 256) {
        int r = i / 27, j = i - r * 27;
        float s = g_b12p[j];
        #pragma unroll
        for (int w = 0; w < 8; w++) s += sH[(w * TILE_R + r) * 32 + j];
        sP[r][j] = (row0 + r < T) ? constrain(s, j) : 0.f;
    }
    __syncthreads();
    if (tid < 27) {
        float s = 0.f;
        #pragma unroll
        for (int r = 0; r < TILE_R; r++) s += sP[r][tid];
        g_P[tid * 4096 + blockIdx.x] = s;   // transposed: coalesced reduce reads
    }
}

// ------------------------- parallel reduce: one block per parameter --------
__global__ void k_reduceP(int nblk, int T) {
    __shared__ float ss[128];
    int j = blockIdx.x;
    int tid = threadIdx.x;
    const float* row = &g_P[j * 4096];
    float s = 0.f;
    for (int b = tid; b < nblk; b += 128) s += row[b];
    ss[tid] = s;
    __syncthreads();
    if (tid < 64) ss[tid] += ss[tid + 64];
    __syncthreads();
    if (tid < 32) {
        float v = ss[tid] + ss[tid + 32];
        #pragma unroll
        for (int o = 16; o; o >>= 1) v += __shfl_down_sync(0xffffffffu, v, o);
        if (tid == 0) g_pm[j] = v / (float)T * c_SCALES[j];
    }
}

// ------------------------- day precompute + S via truncated convolution ----
// 128 days per block (grid ~391) for even SM load; derived constants local.
__global__ void k_day(const float* __restrict__ cin, int T) {
    __shared__ float sx[SK + DAYB];          // tair[base-(SK-1) .. base+DAYB-1]
    __shared__ float pw[SK + 1];
    int base = blockIdx.x * DAYB;
    int tid = threadIdx.x;

    float tau = g_pm[5];
    float a = 1.f - 1.f / tau, invtau = 1.f / tau;
    float S0 = g_pm[6], invSmax = 1.f / g_pm[7], Sinit = g_pm[26];

    for (int i = tid; i < SK + DAYB - 1; i += DAYB) {
        int g = base - (SK - 1) + i;
        sx[i] = (g >= 0 && g < T) ? cin[g * 7 + 1] : 0.f;
    }
    for (int j = tid; j <= SK; j += DAYB) pw[j] = __powf(a, (float)j);
    __syncthreads();

    int t = base + tid;
    if (t >= T) return;

    int Kt = min(t + 1, SK);
    int off = tid + (SK - 1);    // sx index of x_t
    float s0 = 0.f, s1 = 0.f, s2 = 0.f, s3 = 0.f;
    int j = 0;
    for (; j + 4 <= Kt; j += 4) {
        s0 = fmaf(pw[j + 0], sx[off - j - 0], s0);
        s1 = fmaf(pw[j + 1], sx[off - j - 1], s1);
        s2 = fmaf(pw[j + 2], sx[off - j - 2], s2);
        s3 = fmaf(pw[j + 3], sx[off - j - 3], s3);
    }
    for (; j < Kt; j++) s0 = fmaf(pw[j], sx[off - j], s0);
    float S = ((s0 + s1) + (s2 + s3)) * invtau;
    if (t < SK) S = fmaf(pw[t + 1], Sinit, S);
    float fS = fminf(fmaxf(S - S0, 0.f) * invSmax, 1.f);

    float beta = g_pm[4], kappa = g_pm[8], gamma = g_pm[9];
    float bCO2 = g_pm[11], xCO2 = g_pm[12];
    float ETbeta = g_pm[13], ETkappa = g_pm[14], ETchi = g_pm[15];
    float MeltCoef = g_pm[18], CWmax = g_pm[20], ST = g_pm[21], T0p = g_pm[22];
    float Icoef = g_pm[19] / 0.75f;

    float precip = cin[t * 7 + 0], tair = cin[t * 7 + 1], par = cin[t * 7 + 2];
    float vpd = cin[t * 7 + 3], fapar = cin[t * 7 + 4], co2 = cin[t * 7 + 6];

    float fD = fminf(__expf(kappa * vpd), 1.f);
    float fL = __fdividef(1.f, fmaf(gamma, par, 1.f));
    float G = beta * par * fapar * fS * fL;
    float lc = __logf(co2 * (1.f / 380.f));
    float GM = G * fmaf(bCO2, lc, 1.f);
    float fCO2et = fmaf(xCO2, lc, 1.f);
    float TRG = vpd * ETbeta * G * __powf(vpd, -ETkappa) * fCO2et;
    float EV = ETchi * (1.f - fapar) * par;
    float I = (tair > ST) ? precip * fapar * Icoef : 0.f;
    float R = precip - I;
    float cap = CWmax * fapar;
    float meltpot = (tair >= T0p) ? MeltCoef * (tair - T0p) : 0.f;

    g_dayA[t] = make_float4(GM, TRG, fD, EV);
    g_dayB[t] = make_float4(I, R, cap, meltpot);
    g_dayC[t] = (tair < ST) ? 1.f : 0.f;
}

// ------------------------- block-parallel decoupled water scan -------------
// Software-pipelined: next 4-day group prefetched into registers while the
// current group's recurrence runs. Derived constants computed locally.
__global__ void k_scanP(const float* __restrict__ sw, float* __restrict__ pp, int T) {
    if (threadIdx.x != 0) return;
    int start = blockIdx.x * SEG_L;
    if (start >= T) return;
    int end = min(start + SEG_L, T);
    int wstart = max(start - WARM, 0);

    float sd = g_pm[0], fc = g_pm[1], PWP = g_pm[2], tauD = g_pm[3];
    float soilthres = g_pm[10], ETst = g_pm[16], ETnu = g_pm[17];
    float invSD = 1.f / sd, invRange = 1.f / (fc - PWP);
    float invST = 1.f / soilthres, invETst = 1.f / ETst;
    float invTauD = (tauD > 0.f) ? 1.f / tauD : 0.f;
    float c1 = 1.f - invTauD, c2 = fc * sd * invTauD;
    bool smallcw = g_pm[20] <= 1e-8f;
    float a1 = invSD * invRange, b1 = -PWP * invRange;   // REW = theta*a1 + b1

    float theta = g_pm[23], canw = g_pm[24], snow = g_pm[25];
    float sw0 = sw[0], invsw1 = 1.f / sw[1];

    auto step = [&](const float4 da, const float4 db, float cold,
                    float& gpp, float& et) {
        float REW = fmaf(theta, a1, b1);
        float fWmid = REW * invST;
        float pwin = fmaxf(fminf(fWmid, 1.f), 1e-12f);
        float pw = __powf(pwin, ETnu);
        float fW = (REW < soilthres) ? ((REW > 0.01f) ? fWmid : 0.f) : 1.f;
        float fE = fminf(da.z, fW);
        gpp = da.x * fE;
        float transp = da.y * fE * pw;

        float fwm2 = REW * invETst;
        float fWet = (REW < ETst) ? ((REW > 0.01f) ? fwm2 : 0.f) : 1.f;

        float I = db.x, R = db.y, cap = db.z;
        bool over = (I + canw) > cap;
        float tf = smallcw ? (R + I) : (over ? (R + I + canw - cap) : R);
        float canw1 = smallcw ? canw : (over ? cap : canw + I);
        if (canw1 > 1e-8f) fWet = 1.f;
        float evap = da.w * fWet;

        float newsnow = cold * tf;
        tf = tf - newsnow;
        float snn = snow + newsnow;
        float melt = fminf(db.w, snn);
        float snow1 = snn - melt;

        et = transp + evap;
        float etsoil = fmaxf(et - (canw1 + snow1), 0.f);
        float st0 = fmaxf(theta + tf + melt - etsoil, 1e-4f);
        theta = fminf(st0, fmaf(st0, c1, c2));

        canw = fmaxf(canw1 - et, 0.f);
        float rem = fmaxf(et - canw1, 0.f);
        snow = fmaxf(snow1 - rem, 0.f);
    };

    float4 A0, A1, A2, A3, B0, B1, B2, B3, C;
    int t = wstart;
    if (t + 4 <= end) {
        A0 = g_dayA[t]; A1 = g_dayA[t + 1]; A2 = g_dayA[t + 2]; A3 = g_dayA[t + 3];
        B0 = g_dayB[t]; B1 = g_dayB[t + 1]; B2 = g_dayB[t + 2]; B3 = g_dayB[t + 3];
        C = *reinterpret_cast<const float4*>(&g_dayC[t]);
    }
    // warmup: [wstart, start)  (both multiples of 4)
    for (; t + 4 <= start; t += 4) {
        float4 nA0, nA1, nA2, nA3, nB0, nB1, nB2, nB3, nC;
        int tn = t + 4;
        if (tn + 4 <= end) {
            nA0 = g_dayA[tn]; nA1 = g_dayA[tn + 1]; nA2 = g_dayA[tn + 2]; nA3 = g_dayA[tn + 3];
            nB0 = g_dayB[tn]; nB1 = g_dayB[tn + 1]; nB2 = g_dayB[tn + 2]; nB3 = g_dayB[tn + 3];
            nC = *reinterpret_cast<const float4*>(&g_dayC[tn]);
        }
        float g, e;
        step(A0, B0, C.x, g, e);
        step(A1, B1, C.y, g, e);
        step(A2, B2, C.z, g, e);
        step(A3, B3, C.w, g, e);
        A0 = nA0; A1 = nA1; A2 = nA2; A3 = nA3;
        B0 = nB0; B1 = nB1; B2 = nB2; B3 = nB3; C = nC;
    }
    for (; t < start; t++) { float g, e; step(g_dayA[t], g_dayB[t], g_dayC[t], g, e); }
    // output: [start, end)
    for (; t + 4 <= end; t += 4) {
        float4 nA0, nA1, nA2, nA3, nB0, nB1, nB2, nB3, nC;
        int tn = t + 4;
        if (tn + 4 <= end) {
            nA0 = g_dayA[tn]; nA1 = g_dayA[tn + 1]; nA2 = g_dayA[tn + 2]; nA3 = g_dayA[tn + 3];
            nB0 = g_dayB[tn]; nB1 = g_dayB[tn + 1]; nB2 = g_dayB[tn + 2]; nB3 = g_dayB[tn + 3];
            nC = *reinterpret_cast<const float4*>(&g_dayC[tn]);
        }
        float g, e;
        step(A0, B0, C.x, g, e);
        pp[3 * t + 0] = g; pp[3 * t + 1] = e; pp[3 * t + 2] = (theta - sw0) * invsw1;
        step(A1, B1, C.y, g, e);
        pp[3 * t + 3] = g; pp[3 * t + 4] = e; pp[3 * t + 5] = (theta - sw0) * invsw1;
        step(A2, B2, C.z, g, e);
        pp[3 * t + 6] = g; pp[3 * t + 7] = e; pp[3 * t + 8] = (theta - sw0) * invsw1;
        step(A3, B3, C.w, g, e);
        pp[3 * t + 9] = g; pp[3 * t + 10] = e; pp[3 * t + 11] = (theta - sw0) * invsw1;
        A0 = nA0; A1 = nA1; A2 = nA2; A3 = nA3;
        B0 = nB0; B1 = nB1; B2 = nB2; B3 = nB3; C = nC;
    }
    for (; t < end; t++) {   // scalar tail (T not multiple of 4)
        float g, e;
        step(g_dayA[t], g_dayB[t], g_dayC[t], g, e);
        pp[3 * t + 0] = g; pp[3 * t + 1] = e; pp[3 * t + 2] = (theta - sw0) * invsw1;
    }
}

// ------------------------- fused resnet: pp -> y_hat -----------------------
__global__ void k_resnet(const float* __restrict__ pp, const float* __restrict__ rW0,
                         const float* __restrict__ rb0, float* __restrict__ yhat, int T) {
    __shared__ float srW0[3 * HDIM];   // [i][k]
    __shared__ float srb0[HDIM];
    __shared__ float srW12[2 * HDIM];  // transposed: [j][k]
    int tid = threadIdx.x;
    for (int i = tid; i < 3 * HDIM; i += 256) srW0[i] = rW0[i];
    for (int i = tid; i < HDIM; i += 256) srb0[i] = rb0[i];
    for (int i = tid; i < 2 * HDIM; i += 256) {
        int j = i >> 9, k = i & 511;
        srW12[i] = g_W12r[k * 2 + j];
    }
    __syncthreads();
    float bb0 = g_b12r[0], bb1 = g_b12r[1];

    int warp = tid >> 5, lane = tid & 31;
    for (int row = blockIdx.x * 8 + warp; row < T; row += gridDim.x * 8) {
        float x0 = pp[row * 3], x1 = pp[row * 3 + 1], x2 = pp[row * 3 + 2];
        float a0 = 0.f, a1 = 0.f;
        #pragma unroll
        for (int kk = 0; kk < 16; kk++) {
            int k = lane + kk * 32;
            float h = srb0[k];
            h = fmaf(x0, srW0[k], h);
            h = fmaf(x1, srW0[HDIM + k], h);
            h = fmaf(x2, srW0[2 * HDIM + k], h);
            h = h > 0.f ? h : expm1f(h);
            a0 = fmaf(h, srW12[k], a0);
            a1 = fmaf(h, srW12[HDIM + k], a1);
        }
        #pragma unroll
        for (int o = 16; o; o >>= 1) {
            a0 += __shfl_down_sync(0xffffffffu, a0, o);
            a1 += __shfl_down_sync(0xffffffffu, a1, o);
        }
        if (lane == 0) {
            yhat[row * 2 + 0] = a0 + bb0;
            yhat[row * 2 + 1] = a1 + bb1;
        }
    }
}

// ------------------------- launcher ----------------------------------------
extern "C" void kernel_launch(void* const* d_in, const int* in_sizes, int n_in,
                              void* d_out, int out_size) {
    const float* x   = (const float*)d_in[0];
    const float* cin = (const float*)d_in[1];
    const float* sw  = (const float*)d_in[2];
    // d_in[3] = tp (unused)
    const float* pW0 = (const float*)d_in[4];
    const float* pb0 = (const float*)d_in[5];
    const float* pW1 = (const float*)d_in[6];
    const float* pb1 = (const float*)d_in[7];
    const float* pW2 = (const float*)d_in[8];
    const float* pb2 = (const float*)d_in[9];
    const float* rW0 = (const float*)d_in[10];
    const float* rb0 = (const float*)d_in[11];
    const float* rW1 = (const float*)d_in[12];
    const float* rb1 = (const float*)d_in[13];
    const float* rW2 = (const float*)d_in[14];
    const float* rb2 = (const float*)d_in[15];

    int T = in_sizes[0] / 12;
    float* yhat = (float*)d_out;           // [T, 2]
    float* pp = yhat + 2 * T;              // [T, 3]

    int nblk = (T + TILE_R - 1) / TILE_R;
    int nseg = (T + SEG_L - 1) / SEG_L;

    // fold both linear-linear compositions (one launch, independent halves)
    k_folds<<<64, 256>>>(pW1, pb1, pW2, pb2, rW1, rb1, rW2, rb2);

    // parnet (fused): x -> constrained partial sums -> pm
    k_parnet<<<nblk, 256>>>(x, pW0, pb0, T);
    k_reduceP<<<27, 128>>>(nblk, T);

    // PRELES day precompute + block-parallel scan
    k_day<<<(T + DAYB - 1) / DAYB, DAYB>>>(cin, T);
    k_scanP<<<nseg, 32>>>(sw, pp, T);

    // resnet (fused): pp -> y_hat
    k_resnet<<<148, 256>>>(pp, rW0, rb0, yhat, T);
}

// round 16
// speedup vs baseline: 1.9474x; 1.1703x over previous
#include <cuda_runtime.h>
#include <math.h>

#define HDIM 512
#define TILE_R 16
#define SEG_L 64           // output days per scan block
#define WARM 256           // warmup days (contraction burn-in)
#define SK 512             // S-convolution taps
#define DAYB 128           // days per k_day block (512 threads, 4/day)

// ------------------------- scratch (static device globals; no allocs) ------
__device__ float  g_P[27 * 4096];       // transposed partial sums: [j][block]
__device__ float  g_pm[32];             // 27 physical params (scaled means)
__device__ float  g_W12p[HDIM * 32];    // folded parnet W1@W2, padded to 32 cols
__device__ float  g_b12p[32];           // folded parnet bias
__device__ float  g_W12r[HDIM * 2];     // folded resnet rW1@rW2
__device__ float  g_b12r[4];            // folded resnet bias
__device__ float4 g_dayA[50176];        // {GM, TRG, fD, EV}
__device__ float4 g_dayB[50176];        // {I, R, cap, meltpot}
__device__ __align__(16) float g_dayC[50176];  // cold flag

__constant__ float c_SCALES[27] = {400,1,1,1,1,12,10,10,1,1,1,1,1,10,1,1,1,5,1,1,4,1,1,180,1,1,10};

// ------------------------- parameter constraint ----------------------------
__device__ __forceinline__ float clampf(float v, float lo, float hi) {
    return fminf(fmaxf(v, lo), hi);
}
__device__ __forceinline__ float constrain(float v, int j) {
    switch (j) {
        case 0:  return clampf(v, 0.f, 2.f);
        case 1: case 2: case 20: case 21: case 23: case 24: case 25: case 26:
                 return fmaxf(v, 0.f);
        case 4:  return clampf(v, 0.f, 2.5f);
        case 5:  return clampf(v, 0.01f, 3.f);
        case 6:  return clampf(v, -0.2f, 2.1f);
        case 7:  return clampf(v, 0.23f, 3.0f);
        case 8:  return clampf(v, -1.f, 0.f);
        case 9:  return clampf(v, 0.f, 0.7f);
        case 10: case 16: return 1.f / (1.f + expf(-v));
        case 13: return clampf(v, 0.f, 1.0f);
        case 14: return clampf(v, 0.f, 1.2f);
        case 15: return clampf(v, 0.f, 2.5f);
        case 17: return clampf(v, 0.f, 1.f);
        case 19: return clampf(v, 0.f, 1.f / 0.75f);
        default: return v;   // 3, 11, 12, 18, 22
    }
}

// ------------------------- fold both W1@W2 compositions (one launch) -------
__global__ void k_folds(const float* __restrict__ W1p, const float* __restrict__ b1p,
                        const float* __restrict__ W2p, const float* __restrict__ b2p,
                        const float* __restrict__ W1r, const float* __restrict__ b1r,
                        const float* __restrict__ W2r, const float* __restrict__ b2r) {
    __shared__ float sW1[16 * HDIM];       // 32 KB
    __shared__ float sb[32][8];
    int tid = threadIdx.x;
    bool isr = blockIdx.x >= 32;
    const float* W1 = isr ? W1r : W1p;
    const float* b1 = isr ? b1r : b1p;
    const float* W2 = isr ? W2r : W2p;
    const float* b2 = isr ? b2r : b2p;
    float* out  = isr ? g_W12r : g_W12p;
    float* bout = isr ? g_b12r : g_b12p;
    int NOUT = isr ? 2 : 27;
    int OP   = isr ? 2 : 32;       // output pitch
    int blk  = isr ? blockIdx.x - 32 : blockIdx.x;
    int k0 = blk * 16;

    for (int i = tid; i < 16 * HDIM; i += 256)
        sW1[i] = W1[(k0 + (i >> 9)) * HDIM + (i & 511)];
    if (blk == 0) {
        for (int i = tid; i < NOUT * 8; i += 256) {
            int j = i >> 3, l = i & 7;
            float s = 0.f;
            for (int k = l * 64; k < l * 64 + 64; k++)
                s = fmaf(b1[k], W2[k * NOUT + j], s);
            sb[j][l] = s;
        }
    }
    __syncthreads();
    for (int i = tid; i < 16 * OP; i += 256) {
        int kr = i / OP, j = i - kr * OP;
        float s = 0.f;
        if (j < NOUT) {
            const float* w1r = &sW1[kr * HDIM];
            #pragma unroll 4
            for (int m = 0; m < HDIM; m++)
                s = fmaf(w1r[m], W2[m * NOUT + j], s);
        }
        out[(k0 + kr) * OP + j] = s;
    }
    if (blk == 0 && tid < NOUT) {
        float s = b2[tid];
        #pragma unroll
        for (int l = 0; l < 8; l++) s += sb[tid][l];
        bout[tid] = s;
    }
}

// ------------------------- fused parnet: x -> constrained partial sums -----
__global__ void __launch_bounds__(256)
k_parnet(const float* __restrict__ X, const float* __restrict__ W0,
         const float* __restrict__ b0, int T) {
    __shared__ float sH[TILE_R * HDIM];    // 32 KB; reused as partial scratch
    __shared__ float sX[TILE_R][12];
    __shared__ float sP[TILE_R][28];
    int tid = threadIdx.x;
    int warp = tid >> 5, lane = tid & 31;
    int row0 = blockIdx.x * TILE_R;

    if (tid < TILE_R * 12) {
        int r = tid / 12, q = tid - r * 12;
        int gr = row0 + r;
        sX[r][q] = (gr < T) ? X[gr * 12 + q] : 0.f;
    }
    __syncthreads();

    {
        float w0a[12], w0b[12];
        #pragma unroll
        for (int q = 0; q < 12; q++) {
            w0a[q] = W0[q * HDIM + tid];
            w0b[q] = W0[q * HDIM + tid + 256];
        }
        float b0a = b0[tid], b0b = b0[tid + 256];
        #pragma unroll
        for (int r = 0; r < TILE_R; r++) {
            float sa = b0a, sb2 = b0b;
            #pragma unroll
            for (int q = 0; q < 12; q++) {
                float xv = sX[r][q];
                sa  = fmaf(xv, w0a[q], sa);
                sb2 = fmaf(xv, w0b[q], sb2);
            }
            sH[r * HDIM + tid]       = sa  > 0.f ? sa  : expm1f(sa);
            sH[r * HDIM + tid + 256] = sb2 > 0.f ? sb2 : expm1f(sb2);
        }
    }
    __syncthreads();

    float acc[TILE_R];
    #pragma unroll
    for (int r = 0; r < TILE_R; r++) acc[r] = 0.f;
    int kbase = warp * 64;
    #pragma unroll
    for (int kk = 0; kk < 64; kk += 4) {
        int k = kbase + kk;
        float w0 = g_W12p[(k + 0) * 32 + lane];
        float w1 = g_W12p[(k + 1) * 32 + lane];
        float w2 = g_W12p[(k + 2) * 32 + lane];
        float w3 = g_W12p[(k + 3) * 32 + lane];
        #pragma unroll
        for (int r = 0; r < TILE_R; r++) {
            float4 h = *reinterpret_cast<const float4*>(&sH[r * HDIM + k]);
            acc[r] = fmaf(h.x, w0, acc[r]);
            acc[r] = fmaf(h.y, w1, acc[r]);
            acc[r] = fmaf(h.z, w2, acc[r]);
            acc[r] = fmaf(h.w, w3, acc[r]);
        }
    }
    __syncthreads();   // done reading sH
    #pragma unroll
    for (int r = 0; r < TILE_R; r++)
        sH[(warp * TILE_R + r) * 32 + lane] = acc[r];
    __syncthreads();

    for (int i = tid; i < TILE_R * 27; i += 256) {
        int r = i / 27, j = i - r * 27;
        float s = g_b12p[j];
        #pragma unroll
        for (int w = 0; w < 8; w++) s += sH[(w * TILE_R + r) * 32 + j];
        sP[r][j] = (row0 + r < T) ? constrain(s, j) : 0.f;
    }
    __syncthreads();
    if (tid < 27) {
        float s = 0.f;
        #pragma unroll
        for (int r = 0; r < TILE_R; r++) s += sP[r][tid];
        g_P[tid * 4096 + blockIdx.x] = s;   // transposed: coalesced reduce reads
    }
}

// ------------------------- parallel reduce: one block per parameter --------
__global__ void k_reduceP(int nblk, int T) {
    __shared__ float ss[128];
    int j = blockIdx.x;
    int tid = threadIdx.x;
    const float* row = &g_P[j * 4096];
    float s = 0.f;
    for (int b = tid; b < nblk; b += 128) s += row[b];
    ss[tid] = s;
    __syncthreads();
    if (tid < 64) ss[tid] += ss[tid + 64];
    __syncthreads();
    if (tid < 32) {
        float v = ss[tid] + ss[tid + 32];
        #pragma unroll
        for (int o = 16; o; o >>= 1) v += __shfl_down_sync(0xffffffffu, v, o);
        if (tid == 0) g_pm[j] = v / (float)T * c_SCALES[j];
    }
}

// ------------------------- day precompute, 4 threads per day ---------------
// 512 threads cover DAYB=128 days; threads p=0..3 of each quad compute the
// four mod-4 tap partials (same chains as the old s0..s3), combined with the
// same ((s0+s1)+(s2+s3)) tree via shfl. p==0 finishes the day quantities.
__global__ void __launch_bounds__(512)
k_day(const float* __restrict__ cin, int T) {
    __shared__ float sx[SK + DAYB];          // tair[base-(SK-1) .. base+DAYB-1]
    __shared__ float pw[SK + 8];
    int base = blockIdx.x * DAYB;
    int tid = threadIdx.x;

    float tau = g_pm[5];
    float a = 1.f - 1.f / tau, invtau = 1.f / tau;
    float S0 = g_pm[6], invSmax = 1.f / g_pm[7], Sinit = g_pm[26];

    for (int i = tid; i < SK + DAYB - 1; i += 512) {
        int g = base - (SK - 1) + i;
        sx[i] = (g >= 0 && g < T) ? cin[g * 7 + 1] : 0.f;
    }
    for (int j = tid; j <= SK; j += 512) pw[j] = __powf(a, (float)j);
    __syncthreads();

    int d = tid >> 2, p = tid & 3;
    int t = base + d;
    float s = 0.f;
    if (t < T) {
        int Kt = min(t + 1, SK);
        int off = d + (SK - 1);    // sx index of x_t
        for (int j = p; j < Kt; j += 4)
            s = fmaf(pw[j], sx[off - j], s);
    }
    // combine ((s0+s1)+(s2+s3))
    s += __shfl_down_sync(0xffffffffu, s, 1);
    s += __shfl_down_sync(0xffffffffu, s, 2);
    if (p != 0 || t >= T) return;

    float S = s * invtau;
    if (t < SK) S = fmaf(pw[t + 1], Sinit, S);
    float fS = fminf(fmaxf(S - S0, 0.f) * invSmax, 1.f);

    float beta = g_pm[4], kappa = g_pm[8], gamma = g_pm[9];
    float bCO2 = g_pm[11], xCO2 = g_pm[12];
    float ETbeta = g_pm[13], ETkappa = g_pm[14], ETchi = g_pm[15];
    float MeltCoef = g_pm[18], CWmax = g_pm[20], ST = g_pm[21], T0p = g_pm[22];
    float Icoef = g_pm[19] / 0.75f;

    float precip = cin[t * 7 + 0], tair = cin[t * 7 + 1], par = cin[t * 7 + 2];
    float vpd = cin[t * 7 + 3], fapar = cin[t * 7 + 4], co2 = cin[t * 7 + 6];

    float fD = fminf(__expf(kappa * vpd), 1.f);
    float fL = __fdividef(1.f, fmaf(gamma, par, 1.f));
    float G = beta * par * fapar * fS * fL;
    float lc = __logf(co2 * (1.f / 380.f));
    float GM = G * fmaf(bCO2, lc, 1.f);
    float fCO2et = fmaf(xCO2, lc, 1.f);
    float TRG = vpd * ETbeta * G * __powf(vpd, -ETkappa) * fCO2et;
    float EV = ETchi * (1.f - fapar) * par;
    float I = (tair > ST) ? precip * fapar * Icoef : 0.f;
    float R = precip - I;
    float cap = CWmax * fapar;
    float meltpot = (tair >= T0p) ? MeltCoef * (tair - T0p) : 0.f;

    g_dayA[t] = make_float4(GM, TRG, fD, EV);
    g_dayB[t] = make_float4(I, R, cap, meltpot);
    g_dayC[t] = (tair < ST) ? 1.f : 0.f;
}

// ------------------------- block-parallel decoupled water scan -------------
// Software-pipelined: next 4-day group prefetched into registers while the
// current group's recurrence runs. Derived constants computed locally.
__global__ void k_scanP(const float* __restrict__ sw, float* __restrict__ pp, int T) {
    if (threadIdx.x != 0) return;
    int start = blockIdx.x * SEG_L;
    if (start >= T) return;
    int end = min(start + SEG_L, T);
    int wstart = max(start - WARM, 0);

    float sd = g_pm[0], fc = g_pm[1], PWP = g_pm[2], tauD = g_pm[3];
    float soilthres = g_pm[10], ETst = g_pm[16], ETnu = g_pm[17];
    float invSD = 1.f / sd, invRange = 1.f / (fc - PWP);
    float invST = 1.f / soilthres, invETst = 1.f / ETst;
    float invTauD = (tauD > 0.f) ? 1.f / tauD : 0.f;
    float c1 = 1.f - invTauD, c2 = fc * sd * invTauD;
    bool smallcw = g_pm[20] <= 1e-8f;
    float a1 = invSD * invRange, b1 = -PWP * invRange;   // REW = theta*a1 + b1

    float theta = g_pm[23], canw = g_pm[24], snow = g_pm[25];
    float sw0 = sw[0], invsw1 = 1.f / sw[1];

    auto step = [&](const float4 da, const float4 db, float cold,
                    float& gpp, float& et) {
        float REW = fmaf(theta, a1, b1);
        float fWmid = REW * invST;
        float pwin = fmaxf(fminf(fWmid, 1.f), 1e-12f);
        float pw = __powf(pwin, ETnu);
        float fW = (REW < soilthres) ? ((REW > 0.01f) ? fWmid : 0.f) : 1.f;
        float fE = fminf(da.z, fW);
        gpp = da.x * fE;
        float transp = da.y * fE * pw;

        float fwm2 = REW * invETst;
        float fWet = (REW < ETst) ? ((REW > 0.01f) ? fwm2 : 0.f) : 1.f;

        float I = db.x, R = db.y, cap = db.z;
        bool over = (I + canw) > cap;
        float tf = smallcw ? (R + I) : (over ? (R + I + canw - cap) : R);
        float canw1 = smallcw ? canw : (over ? cap : canw + I);
        if (canw1 > 1e-8f) fWet = 1.f;
        float evap = da.w * fWet;

        float newsnow = cold * tf;
        tf = tf - newsnow;
        float snn = snow + newsnow;
        float melt = fminf(db.w, snn);
        float snow1 = snn - melt;

        et = transp + evap;
        float etsoil = fmaxf(et - (canw1 + snow1), 0.f);
        float st0 = fmaxf(theta + tf + melt - etsoil, 1e-4f);
        theta = fminf(st0, fmaf(st0, c1, c2));

        canw = fmaxf(canw1 - et, 0.f);
        float rem = fmaxf(et - canw1, 0.f);
        snow = fmaxf(snow1 - rem, 0.f);
    };

    float4 A0, A1, A2, A3, B0, B1, B2, B3, C;
    int t = wstart;
    if (t + 4 <= end) {
        A0 = g_dayA[t]; A1 = g_dayA[t + 1]; A2 = g_dayA[t + 2]; A3 = g_dayA[t + 3];
        B0 = g_dayB[t]; B1 = g_dayB[t + 1]; B2 = g_dayB[t + 2]; B3 = g_dayB[t + 3];
        C = *reinterpret_cast<const float4*>(&g_dayC[t]);
    }
    // warmup: [wstart, start)  (both multiples of 4)
    for (; t + 4 <= start; t += 4) {
        float4 nA0, nA1, nA2, nA3, nB0, nB1, nB2, nB3, nC;
        int tn = t + 4;
        if (tn + 4 <= end) {
            nA0 = g_dayA[tn]; nA1 = g_dayA[tn + 1]; nA2 = g_dayA[tn + 2]; nA3 = g_dayA[tn + 3];
            nB0 = g_dayB[tn]; nB1 = g_dayB[tn + 1]; nB2 = g_dayB[tn + 2]; nB3 = g_dayB[tn + 3];
            nC = *reinterpret_cast<const float4*>(&g_dayC[tn]);
        }
        float g, e;
        step(A0, B0, C.x, g, e);
        step(A1, B1, C.y, g, e);
        step(A2, B2, C.z, g, e);
        step(A3, B3, C.w, g, e);
        A0 = nA0; A1 = nA1; A2 = nA2; A3 = nA3;
        B0 = nB0; B1 = nB1; B2 = nB2; B3 = nB3; C = nC;
    }
    for (; t < start; t++) { float g, e; step(g_dayA[t], g_dayB[t], g_dayC[t], g, e); }
    // output: [start, end)
    for (; t + 4 <= end; t += 4) {
        float4 nA0, nA1, nA2, nA3, nB0, nB1, nB2, nB3, nC;
        int tn = t + 4;
        if (tn + 4 <= end) {
            nA0 = g_dayA[tn]; nA1 = g_dayA[tn + 1]; nA2 = g_dayA[tn + 2]; nA3 = g_dayA[tn + 3];
            nB0 = g_dayB[tn]; nB1 = g_dayB[tn + 1]; nB2 = g_dayB[tn + 2]; nB3 = g_dayB[tn + 3];
            nC = *reinterpret_cast<const float4*>(&g_dayC[tn]);
        }
        float g, e;
        step(A0, B0, C.x, g, e);
        pp[3 * t + 0] = g; pp[3 * t + 1] = e; pp[3 * t + 2] = (theta - sw0) * invsw1;
        step(A1, B1, C.y, g, e);
        pp[3 * t + 3] = g; pp[3 * t + 4] = e; pp[3 * t + 5] = (theta - sw0) * invsw1;
        step(A2, B2, C.z, g, e);
        pp[3 * t + 6] = g; pp[3 * t + 7] = e; pp[3 * t + 8] = (theta - sw0) * invsw1;
        step(A3, B3, C.w, g, e);
        pp[3 * t + 9] = g; pp[3 * t + 10] = e; pp[3 * t + 11] = (theta - sw0) * invsw1;
        A0 = nA0; A1 = nA1; A2 = nA2; A3 = nA3;
        B0 = nB0; B1 = nB1; B2 = nB2; B3 = nB3; C = nC;
    }
    for (; t < end; t++) {   // scalar tail (T not multiple of 4)
        float g, e;
        step(g_dayA[t], g_dayB[t], g_dayC[t], g, e);
        pp[3 * t + 0] = g; pp[3 * t + 1] = e; pp[3 * t + 2] = (theta - sw0) * invsw1;
    }
}

// ------------------------- fused resnet: pp -> y_hat -----------------------
__global__ void k_resnet(const float* __restrict__ pp, const float* __restrict__ rW0,
                         const float* __restrict__ rb0, float* __restrict__ yhat, int T) {
    __shared__ float srW0[3 * HDIM];   // [i][k]
    __shared__ float srb0[HDIM];
    __shared__ float srW12[2 * HDIM];  // transposed: [j][k]
    int tid = threadIdx.x;
    for (int i = tid; i < 3 * HDIM; i += 256) srW0[i] = rW0[i];
    for (int i = tid; i < HDIM; i += 256) srb0[i] = rb0[i];
    for (int i = tid; i < 2 * HDIM; i += 256) {
        int j = i >> 9, k = i & 511;
        srW12[i] = g_W12r[k * 2 + j];
    }
    __syncthreads();
    float bb0 = g_b12r[0], bb1 = g_b12r[1];

    int warp = tid >> 5, lane = tid & 31;
    for (int row = blockIdx.x * 8 + warp; row < T; row += gridDim.x * 8) {
        float x0 = pp[row * 3], x1 = pp[row * 3 + 1], x2 = pp[row * 3 + 2];
        float a0 = 0.f, a1 = 0.f;
        #pragma unroll
        for (int kk = 0; kk < 16; kk++) {
            int k = lane + kk * 32;
            float h = srb0[k];
            h = fmaf(x0, srW0[k], h);
            h = fmaf(x1, srW0[HDIM + k], h);
            h = fmaf(x2, srW0[2 * HDIM + k], h);
            h = h > 0.f ? h : expm1f(h);
            a0 = fmaf(h, srW12[k], a0);
            a1 = fmaf(h, srW12[HDIM + k], a1);
        }
        #pragma unroll
        for (int o = 16; o; o >>= 1) {
            a0 += __shfl_down_sync(0xffffffffu, a0, o);
            a1 += __shfl_down_sync(0xffffffffu, a1, o);
        }
        if (lane == 0) {
            yhat[row * 2 + 0] = a0 + bb0;
            yhat[row * 2 + 1] = a1 + bb1;
        }
    }
}

// ------------------------- launcher ----------------------------------------
extern "C" void kernel_launch(void* const* d_in, const int* in_sizes, int n_in,
                              void* d_out, int out_size) {
    const float* x   = (const float*)d_in[0];
    const float* cin = (const float*)d_in[1];
    const float* sw  = (const float*)d_in[2];
    // d_in[3] = tp (unused)
    const float* pW0 = (const float*)d_in[4];
    const float* pb0 = (const float*)d_in[5];
    const float* pW1 = (const float*)d_in[6];
    const float* pb1 = (const float*)d_in[7];
    const float* pW2 = (const float*)d_in[8];
    const float* pb2 = (const float*)d_in[9];
    const float* rW0 = (const float*)d_in[10];
    const float* rb0 = (const float*)d_in[11];
    const float* rW1 = (const float*)d_in[12];
    const float* rb1 = (const float*)d_in[13];
    const float* rW2 = (const float*)d_in[14];
    const float* rb2 = (const float*)d_in[15];

    int T = in_sizes[0] / 12;
    float* yhat = (float*)d_out;           // [T, 2]
    float* pp = yhat + 2 * T;              // [T, 3]

    int nblk = (T + TILE_R - 1) / TILE_R;
    int nseg = (T + SEG_L - 1) / SEG_L;

    // fold both linear-linear compositions (one launch, independent halves)
    k_folds<<<64, 256>>>(pW1, pb1, pW2, pb2, rW1, rb1, rW2, rb2);

    // parnet (fused): x -> constrained partial sums -> pm
    k_parnet<<<nblk, 256>>>(x, pW0, pb0, T);
    k_reduceP<<<27, 128>>>(nblk, T);

    // PRELES day precompute + block-parallel scan
    k_day<<<(T + DAYB - 1) / DAYB, 512>>>(cin, T);
    k_scanP<<<nseg, 32>>>(sw, pp, T);

    // resnet (fused): pp -> y_hat
    k_resnet<<<296, 256>>>(pp, rW0, rb0, yhat, T);
}